// round 7
// baseline (speedup 1.0000x reference)
#include <cuda_runtime.h>
#include <cstdint>
#include <math.h>

// ---------------------------------------------------------------------------
// LegalMultiHeadAttention — Round 7: 16-warp CTAs (512 thr), warp tile 32x64,
// 4 warps/SMSP for latency hiding. 3-stage cp.async pipeline, tf32 conversion
// hoisted to producers. CTA tile (MW*32)x(NW*64), MW*NW=16.
//   B=2, S=4096, D_MODEL=1024, H=4, D_K=256.
// ---------------------------------------------------------------------------

#define SEQ    4096
#define DK     256
#define DM     1024
#define NH     4
#define NB     2
#define BS_TOT (NB*SEQ)          // 8192

__device__ float g_Q [(size_t)NH*BS_TOT*DK];   // tf32-rounded
__device__ float g_K [(size_t)NH*BS_TOT*DK];   // tf32-rounded
__device__ float g_V [(size_t)NH*BS_TOT*DK];   // tf32-rounded
__device__ float g_VT[(size_t)NH*BS_TOT*DK];   // tf32-rounded
__device__ float g_HO[(size_t)BS_TOT*DM];      // tf32-rounded
__device__ float g_WT[(size_t)3*NH*DK*DM];     // tf32-rounded
__device__ float g_WoT[(size_t)DM*DM];         // tf32-rounded
__device__ float g_attn_fallback[(size_t)NH*NB*SEQ*SEQ];

__device__ __forceinline__ uint32_t smem_u32(const void* p) {
    uint32_t a;
    asm("{ .reg .u64 t; cvta.to.shared.u64 t, %1; cvt.u32.u64 %0, t; }"
        : "=r"(a) : "l"(p));
    return a;
}
__device__ __forceinline__ uint32_t f2tf32(float x) {
    uint32_t u;
    asm("cvt.rna.tf32.f32 %0, %1;" : "=r"(u) : "f"(x));
    return u;
}
__device__ __forceinline__ float roundtf(float x) { return __uint_as_float(f2tf32(x)); }

__device__ __forceinline__ void mma_tf32(float& c0, float& c1, float& c2, float& c3,
                                         uint32_t a0, uint32_t a1, uint32_t a2, uint32_t a3,
                                         uint32_t b0, uint32_t b1) {
    asm volatile(
        "mma.sync.aligned.m16n8k8.row.col.f32.tf32.tf32.f32 "
        "{%0,%1,%2,%3}, {%4,%5,%6,%7}, {%8,%9}, {%0,%1,%2,%3};"
        : "+f"(c0), "+f"(c1), "+f"(c2), "+f"(c3)
        : "r"(a0), "r"(a1), "r"(a2), "r"(a3), "r"(b0), "r"(b1));
}
__device__ __forceinline__ void cp16(uint32_t dst, const void* src) {
    asm volatile("cp.async.cg.shared.global [%0], [%1], 16;" :: "r"(dst), "l"(src));
}

#define NSTAGE 3
#define BUF_WORDS 12288                      // (MW*32 + NW*64)/8*... = 384 rows * 32
#define SMEM_BYTES (NSTAGE*BUF_WORDS*4)      // 147456

// ---------------------------------------------------------------------------
// GEMM NT: C[m,n] = alpha*sum_k A[m,k]*B[n,k] (+bias[n]).
// 512 threads = 16 warps arranged MW (M) x NW (N); warp tile 32x64.
// smem word layout per tile: ((row>>3)*64 + (row&7)*8 + (kc^(row&7)))*4 + tg
// Requires MW*32 + NW*64 == 384 (true for MW,NW in {(4,4),(8,2)}).
// ---------------------------------------------------------------------------
template<int MW, int NW, bool CVTA, bool HASBIAS, bool ROUND_OUT>
__device__ __forceinline__ void gemm_cp(const float* __restrict__ A, int lda,
                                        const float* __restrict__ B, int ldb,
                                        float* __restrict__ C, int ldc,
                                        int K, float alpha, const float* __restrict__ bias)
{
    extern __shared__ float smem[];
    const uint32_t sbase = smem_u32(smem);

    const int tid  = threadIdx.x;           // 512
    const int wid  = tid >> 5;
    const int lane = tid & 31;
    const int grp  = lane >> 2;
    const int tg   = lane & 3;
    const int wm   = (wid / NW) * 32;
    const int wn   = (wid % NW) * 64;

    const long bm = (long)blockIdx.y * (MW * 32);
    const long bn = (long)blockIdx.x * (NW * 64);
    A += bm * (long)lda;
    B += bn * (long)ldb;

    const int sm_ = tid >> 3;                // 0..63
    const int skc = tid & 7;

    float acc[2][8][4];
#pragma unroll
    for (int i = 0; i < 2; i++)
#pragma unroll
        for (int j = 0; j < 8; j++)
#pragma unroll
            for (int r = 0; r < 4; r++) acc[i][j][r] = 0.0f;

    const int NIT = K >> 5;
    const int AWORDS = MW * 1024;            // MW*32 rows * 32 words

    auto stage_copy = [&](int stage, int buf) {
        const uint32_t db = sbase + (uint32_t)buf * (BUF_WORDS * 4);
        const float* Ak = A + stage * 32;
        const float* Bk = B + stage * 32;
#pragma unroll
        for (int c = 0; c < MW / 2; c++) {   // A rows: MW*32, 64 rows per pass
            const int m = sm_ + c * 64;
            const int g = m & 7;
            const int chunk = (m >> 3) * 64 + g * 8 + (skc ^ g);
            cp16(db + (uint32_t)chunk * 16, Ak + (long)m * lda + skc * 4);
        }
        const uint32_t dbB = db + (uint32_t)AWORDS * 4;
#pragma unroll
        for (int c = 0; c < NW; c++) {       // B rows: NW*64
            const int n = sm_ + c * 64;
            const int g = n & 7;
            const int chunk = (n >> 3) * 64 + g * 8 + (skc ^ g);
            cp16(dbB + (uint32_t)chunk * 16, Bk + (long)n * ldb + skc * 4);
        }
        asm volatile("cp.async.commit_group;" ::: "memory");
    };

    stage_copy(0, 0);
    stage_copy(1, 1);

    int cbuf = 0;
#pragma unroll 1
    for (int it = 0; it < NIT; it++) {
        asm volatile("cp.async.wait_group %0;" :: "n"(NSTAGE - 2) : "memory");
        __syncthreads();
        if (it + 2 < NIT) {
            int nb = cbuf + 2; if (nb >= NSTAGE) nb -= NSTAGE;
            stage_copy(it + 2, nb);
        }

        const float* sA = smem + cbuf * BUF_WORDS;
        const float* sB = sA + AWORDS;

#pragma unroll
        for (int ks = 0; ks < 4; ks++) {
            uint32_t af[2][4];
#pragma unroll
            for (int mt = 0; mt < 2; mt++) {
#pragma unroll
                for (int i = 0; i < 2; i++) {
                    const int base = ((wm >> 3) + mt * 2 + i) * 64 + grp * 8;
                    const float v0 = sA[(base + ((2 * ks + 0) ^ grp)) * 4 + tg];
                    const float v1 = sA[(base + ((2 * ks + 1) ^ grp)) * 4 + tg];
                    af[mt][i]     = CVTA ? f2tf32(v0) : __float_as_uint(v0);
                    af[mt][i + 2] = CVTA ? f2tf32(v1) : __float_as_uint(v1);
                }
            }
            uint32_t bf[8][2];
#pragma unroll
            for (int nt = 0; nt < 8; nt++) {
                const int base = ((wn >> 3) + nt) * 64 + grp * 8;
                bf[nt][0] = __float_as_uint(sB[(base + ((2 * ks + 0) ^ grp)) * 4 + tg]);
                bf[nt][1] = __float_as_uint(sB[(base + ((2 * ks + 1) ^ grp)) * 4 + tg]);
            }
#pragma unroll
            for (int mt = 0; mt < 2; mt++)
#pragma unroll
                for (int nt = 0; nt < 8; nt++)
                    mma_tf32(acc[mt][nt][0], acc[mt][nt][1], acc[mt][nt][2], acc[mt][nt][3],
                             af[mt][0], af[mt][1], af[mt][2], af[mt][3],
                             bf[nt][0], bf[nt][1]);
        }
        cbuf++; if (cbuf >= NSTAGE) cbuf = 0;
    }

#pragma unroll
    for (int mt = 0; mt < 2; mt++) {
        const long r0 = bm + wm + mt * 16 + grp;
#pragma unroll
        for (int nt = 0; nt < 8; nt++) {
            const int cn = (int)bn + wn + nt * 8 + 2 * tg;
            float2 v0, v1;
            v0.x = acc[mt][nt][0] * alpha;
            v0.y = acc[mt][nt][1] * alpha;
            v1.x = acc[mt][nt][2] * alpha;
            v1.y = acc[mt][nt][3] * alpha;
            if (HASBIAS) {
                const float b0 = bias[cn], b1 = bias[cn + 1];
                v0.x += b0; v0.y += b1;
                v1.x += b0; v1.y += b1;
            }
            if (ROUND_OUT) {
                v0.x = roundtf(v0.x); v0.y = roundtf(v0.y);
                v1.x = roundtf(v1.x); v1.y = roundtf(v1.y);
            }
            *(float2*)(C + r0 * (long)ldc + cn)       = v0;
            *(float2*)(C + (r0 + 8) * (long)ldc + cn) = v1;
        }
    }
}

// ---------------------------------------------------------------------------
// transpose (+tf32 round): dst[c][r] = round(src[r][c])
// ---------------------------------------------------------------------------
__global__ void __launch_bounds__(256) trans_kernel(const float* __restrict__ in,
                                                    int which, int R, int C)
{
    __shared__ float t[32][33];
    const int z = blockIdx.z;
    const float* src;
    float* dst;
    if (which == 4)      { src = g_V + (size_t)z * R * C;  dst = g_VT + (size_t)z * R * C; }
    else if (which == 3) { src = in;                        dst = g_WoT; }
    else                 { src = in + (size_t)z * R * C;    dst = g_WT + ((size_t)which * NH + z) * R * C; }

    const int c0 = blockIdx.x * 32, r0 = blockIdx.y * 32;
    const int tx = threadIdx.x & 31, ty = threadIdx.x >> 5;
#pragma unroll
    for (int i = 0; i < 4; i++)
        t[ty + i * 8][tx] = roundtf(src[(size_t)(r0 + ty + i * 8) * C + c0 + tx]);
    __syncthreads();
#pragma unroll
    for (int i = 0; i < 4; i++)
        dst[(size_t)(c0 + ty + i * 8) * R + r0 + tx] = t[tx][ty + i * 8];
}

// ---------------------------------------------------------------------------
__global__ void __launch_bounds__(512, 1) proj_tc(
    const float* __restrict__ q, const float* __restrict__ k, const float* __restrict__ v,
    const float* __restrict__ bq, const float* __restrict__ bk, const float* __restrict__ bv)
{
    const int z = blockIdx.z, mat = z >> 2, head = z & 3;
    const float* A    = mat == 0 ? q  : mat == 1 ? k  : v;
    const float* B    = g_WT + (size_t)z * DK * DM;
    const float* bias = (mat == 0 ? bq : mat == 1 ? bk : bv) + head * DK;
    float* C = (mat == 0 ? g_Q : mat == 1 ? g_K : g_V) + (size_t)head * BS_TOT * DK;
    gemm_cp<4, 4, true, true, true>(A, DM, B, DM, C, DK, DM, 1.0f, bias);   // 128x256
}

__global__ void __launch_bounds__(512, 1) scores_tc(float* __restrict__ attn_out)
{
    float* attn = attn_out ? attn_out : g_attn_fallback;
    const int z = blockIdx.z;
    gemm_cp<8, 2, false, false, false>(g_Q + (size_t)z * SEQ * DK, DK,       // 256x128
                                       g_K + (size_t)z * SEQ * DK, DK,
                                       attn + (size_t)z * SEQ * SEQ, SEQ, DK, 0.0625f, nullptr);
}

__global__ void __launch_bounds__(512, 1) av_tc(const float* __restrict__ attn_out)
{
    const float* attn = attn_out ? attn_out : g_attn_fallback;
    const int z = blockIdx.z, h = z >> 1, b = z & 1;
    gemm_cp<4, 4, true, false, true>(attn + (size_t)z * SEQ * SEQ, SEQ,      // 128x256
                                     g_VT + (size_t)z * DK * SEQ, SEQ,
                                     g_HO + (size_t)b * SEQ * DM + h * DK, DM, SEQ, 1.0f, nullptr);
}

__global__ void __launch_bounds__(512, 1) outproj_tc(const float* __restrict__ bo,
                                                     float* __restrict__ out)
{
    gemm_cp<4, 4, false, true, false>(g_HO, DM, g_WoT, DM, out, DM, DM, 1.0f, bo);
}

// ---------------------------------------------------------------------------
// row softmax in place: float4 I/O, __expf
// ---------------------------------------------------------------------------
__global__ void __launch_bounds__(256) softmax_kernel(float* __restrict__ attn_out)
{
    float* attn = attn_out ? attn_out : g_attn_fallback;
    float4* row = (float4*)(attn + (size_t)blockIdx.x * SEQ);
    const int tid = threadIdx.x;

    float4 v[4];
    float m = -1e30f;
#pragma unroll
    for (int i = 0; i < 4; i++) {
        v[i] = row[tid + i * 256];
        m = fmaxf(m, fmaxf(fmaxf(v[i].x, v[i].y), fmaxf(v[i].z, v[i].w)));
    }

    __shared__ float red_max[8];
    __shared__ float red_sum[8];
#pragma unroll
    for (int o = 16; o > 0; o >>= 1) m = fmaxf(m, __shfl_xor_sync(0xffffffffu, m, o));
    if ((tid & 31) == 0) red_max[tid >> 5] = m;
    __syncthreads();
    float mb = red_max[0];
#pragma unroll
    for (int i = 1; i < 8; i++) mb = fmaxf(mb, red_max[i]);

    float s = 0.0f;
#pragma unroll
    for (int i = 0; i < 4; i++) {
        v[i].x = __expf(v[i].x - mb); v[i].y = __expf(v[i].y - mb);
        v[i].z = __expf(v[i].z - mb); v[i].w = __expf(v[i].w - mb);
        s += (v[i].x + v[i].y) + (v[i].z + v[i].w);
    }
#pragma unroll
    for (int o = 16; o > 0; o >>= 1) s += __shfl_xor_sync(0xffffffffu, s, o);
    if ((tid & 31) == 0) red_sum[tid >> 5] = s;
    __syncthreads();
    float tot = 0.0f;
#pragma unroll
    for (int i = 0; i < 8; i++) tot += red_sum[i];
    const float inv = 1.0f / tot;

#pragma unroll
    for (int i = 0; i < 4; i++) {
        v[i].x *= inv; v[i].y *= inv; v[i].z *= inv; v[i].w *= inv;
        row[tid + i * 256] = v[i];
    }
}

// ---------------------------------------------------------------------------
extern "C" void kernel_launch(void* const* d_in, const int* in_sizes, int n_in,
                              void* d_out, int out_size)
{
    const float* q  = (const float*)d_in[0];
    const float* k  = (const float*)d_in[1];
    const float* v  = (const float*)d_in[2];
    const float* Wq = (const float*)d_in[3];
    const float* bq = (const float*)d_in[4];
    const float* Wk = (const float*)d_in[5];
    const float* bk = (const float*)d_in[6];
    const float* Wv = (const float*)d_in[7];
    const float* bv = (const float*)d_in[8];
    const float* Wo = (const float*)d_in[9];
    const float* bo = (const float*)d_in[10];

    float* out = (float*)d_out;
    const long OUT_ELEMS  = (long)NB * SEQ * DM;
    const long ATTN_ELEMS = (long)NH * NB * SEQ * SEQ;
    float* attn_out = nullptr;
    if ((long)out_size >= OUT_ELEMS + ATTN_ELEMS) attn_out = out + OUT_ELEMS;

    cudaFuncSetAttribute(proj_tc,    cudaFuncAttributeMaxDynamicSharedMemorySize, SMEM_BYTES);
    cudaFuncSetAttribute(scores_tc,  cudaFuncAttributeMaxDynamicSharedMemorySize, SMEM_BYTES);
    cudaFuncSetAttribute(av_tc,      cudaFuncAttributeMaxDynamicSharedMemorySize, SMEM_BYTES);
    cudaFuncSetAttribute(outproj_tc, cudaFuncAttributeMaxDynamicSharedMemorySize, SMEM_BYTES);

    trans_kernel<<<dim3(8, 32, 4),  256>>>(Wq, 0, DM, DK);
    trans_kernel<<<dim3(8, 32, 4),  256>>>(Wk, 1, DM, DK);
    trans_kernel<<<dim3(8, 32, 4),  256>>>(Wv, 2, DM, DK);
    trans_kernel<<<dim3(32, 32, 1), 256>>>(Wo, 3, DM, DM);

    proj_tc<<<dim3(1, 64, 12), 512, SMEM_BYTES>>>(q, k, v, bq, bk, bv);

    trans_kernel<<<dim3(8, 128, 8), 256>>>(nullptr, 4, SEQ, DK);

    scores_tc<<<dim3(32, 16, 8), 512, SMEM_BYTES>>>(attn_out);

    softmax_kernel<<<dim3(NH * NB * SEQ), 256>>>(attn_out);

    av_tc<<<dim3(1, 32, 8), 512, SMEM_BYTES>>>(attn_out);

    outproj_tc<<<dim3(4, 64, 1), 512, SMEM_BYTES>>>(bo, out);
}

// round 8
// speedup vs baseline: 1.1160x; 1.1160x over previous
#include <cuda_runtime.h>
#include <cstdint>
#include <math.h>

// ---------------------------------------------------------------------------
// LegalMultiHeadAttention — Round 8: R6 geometry (8 warps, 64x64 warp tile)
// + softmax fused away: scores writes exp(score) + row partial sums;
// invsum kernel computes 1/rowsum; av scales outputs by invsum and writes the
// normalized attn back from smem (each attn element staged exactly once).
//   B=2, S=4096, D_MODEL=1024, H=4, D_K=256.
// ---------------------------------------------------------------------------

#define SEQ    4096
#define DK     256
#define DM     1024
#define NH     4
#define NB     2
#define BS_TOT (NB*SEQ)          // 8192
#define NROWS  (NH*NB*SEQ)       // 32768 attn rows

__device__ float g_Q [(size_t)NH*BS_TOT*DK];   // tf32-rounded
__device__ float g_K [(size_t)NH*BS_TOT*DK];   // tf32-rounded
__device__ float g_V [(size_t)NH*BS_TOT*DK];   // tf32-rounded
__device__ float g_VT[(size_t)NH*BS_TOT*DK];   // tf32-rounded
__device__ float g_HO[(size_t)BS_TOT*DM];      // tf32-rounded
__device__ float g_WT[(size_t)3*NH*DK*DM];     // tf32-rounded
__device__ float g_WoT[(size_t)DM*DM];         // tf32-rounded
__device__ float g_psum[(size_t)NROWS*64];     // per-row, per-64col partial sums
__device__ float g_invsum[(size_t)NROWS];      // 1 / row sum
__device__ float g_attn_fallback[(size_t)NH*NB*SEQ*SEQ];

__device__ __forceinline__ uint32_t smem_u32(const void* p) {
    uint32_t a;
    asm("{ .reg .u64 t; cvta.to.shared.u64 t, %1; cvt.u32.u64 %0, t; }"
        : "=r"(a) : "l"(p));
    return a;
}
__device__ __forceinline__ uint32_t f2tf32(float x) {
    uint32_t u;
    asm("cvt.rna.tf32.f32 %0, %1;" : "=r"(u) : "f"(x));
    return u;
}
__device__ __forceinline__ float roundtf(float x) { return __uint_as_float(f2tf32(x)); }

__device__ __forceinline__ void mma_tf32(float& c0, float& c1, float& c2, float& c3,
                                         uint32_t a0, uint32_t a1, uint32_t a2, uint32_t a3,
                                         uint32_t b0, uint32_t b1) {
    asm volatile(
        "mma.sync.aligned.m16n8k8.row.col.f32.tf32.tf32.f32 "
        "{%0,%1,%2,%3}, {%4,%5,%6,%7}, {%8,%9}, {%0,%1,%2,%3};"
        : "+f"(c0), "+f"(c1), "+f"(c2), "+f"(c3)
        : "r"(a0), "r"(a1), "r"(a2), "r"(a3), "r"(b0), "r"(b1));
}
__device__ __forceinline__ void cp16(uint32_t dst, const void* src) {
    asm volatile("cp.async.cg.shared.global [%0], [%1], 16;" :: "r"(dst), "l"(src));
}

#define NSTAGE 3
#define BUF_WORDS 12288                      // (WGM+WGN)*2048 = 12288
#define SMEM_BYTES (NSTAGE*BUF_WORDS*4)      // 147456

// ---------------------------------------------------------------------------
// GEMM NT: C[m,n] = alpha*sum_k A[m,k]*B[n,k] (+bias[n]).
// 256 threads = 8 warps (WGM x WGN), warp tile 64x64.
// MODE 0: plain. MODE 1: scores (write exp, emit psum to aux).
// MODE 2: av (write invrow-scaled A tiles back to aux; scale C rows by invrow).
// ---------------------------------------------------------------------------
template<int WGM, int WGN, bool CVTA, bool HASBIAS, bool ROUND_OUT, int MODE>
__device__ __forceinline__ void gemm_cp(const float* __restrict__ A, int lda,
                                        const float* __restrict__ B, int ldb,
                                        float* __restrict__ C, int ldc,
                                        int K, float alpha, const float* __restrict__ bias,
                                        float* __restrict__ aux,
                                        const float* __restrict__ invrow)
{
    extern __shared__ float smem[];
    const uint32_t sbase = smem_u32(smem);

    const int tid  = threadIdx.x;           // 256
    const int wid  = tid >> 5;
    const int lane = tid & 31;
    const int grp  = lane >> 2;
    const int tg   = lane & 3;
    const int wm   = (wid / WGN) * 64;
    const int wn   = (wid % WGN) * 64;

    const long bm = (long)blockIdx.y * (WGM * 64);
    const long bn = (long)blockIdx.x * (WGN * 64);
    A += bm * (long)lda;
    B += bn * (long)ldb;

    const int sm_ = tid >> 3;
    const int skc = tid & 7;

    // MODE 2: per-thread inverse row sums for the A rows this thread stages
    float invs[2 * WGM];
    if (MODE == 2) {
#pragma unroll
        for (int c = 0; c < 2 * WGM; c++)
            invs[c] = invrow[bm + sm_ + c * 32];
    }

    float acc[4][8][4];
#pragma unroll
    for (int i = 0; i < 4; i++)
#pragma unroll
        for (int j = 0; j < 8; j++)
#pragma unroll
            for (int r = 0; r < 4; r++) acc[i][j][r] = 0.0f;

    const int NIT = K >> 5;
    const int AWORDS = WGM * 2048;

    auto stage_copy = [&](int stage, int buf) {
        const uint32_t db = sbase + (uint32_t)buf * (BUF_WORDS * 4);
        const float* Ak = A + stage * 32;
        const float* Bk = B + stage * 32;
#pragma unroll
        for (int c = 0; c < 2 * WGM; c++) {
            const int m = sm_ + c * 32;
            const int g = m & 7;
            const int chunk = (m >> 3) * 64 + g * 8 + (skc ^ g);
            cp16(db + (uint32_t)chunk * 16, Ak + (long)m * lda + skc * 4);
        }
        const uint32_t dbB = db + (uint32_t)AWORDS * 4;
#pragma unroll
        for (int c = 0; c < 2 * WGN; c++) {
            const int n = sm_ + c * 32;
            const int g = n & 7;
            const int chunk = (n >> 3) * 64 + g * 8 + (skc ^ g);
            cp16(dbB + (uint32_t)chunk * 16, Bk + (long)n * ldb + skc * 4);
        }
        asm volatile("cp.async.commit_group;" ::: "memory");
    };

    stage_copy(0, 0);
    stage_copy(1, 1);

    int cbuf = 0;
#pragma unroll 1
    for (int it = 0; it < NIT; it++) {
        asm volatile("cp.async.wait_group %0;" :: "n"(NSTAGE - 2) : "memory");
        __syncthreads();
        if (it + 2 < NIT) {
            int nb = cbuf + 2; if (nb >= NSTAGE) nb -= NSTAGE;
            stage_copy(it + 2, nb);
        }

        const float* sA = smem + cbuf * BUF_WORDS;
        const float* sB = sA + AWORDS;

        // MODE 2: write normalized attn tile back (each element staged once)
        if (MODE == 2) {
#pragma unroll
            for (int c = 0; c < 2 * WGM; c++) {
                const int m = sm_ + c * 32;
                const int g = m & 7;
                const int chunk = (m >> 3) * 64 + g * 8 + (skc ^ g);
                float4 e = *(const float4*)(sA + chunk * 4);
                e.x *= invs[c]; e.y *= invs[c]; e.z *= invs[c]; e.w *= invs[c];
                *(float4*)(aux + (bm + m) * (long)lda + it * 32 + skc * 4) = e;
            }
        }

#pragma unroll
        for (int ks = 0; ks < 4; ks++) {
            uint32_t af[4][4];
#pragma unroll
            for (int mt = 0; mt < 4; mt++) {
#pragma unroll
                for (int i = 0; i < 2; i++) {
                    const int base = ((wm >> 3) + mt * 2 + i) * 64 + grp * 8;
                    const float v0 = sA[(base + ((2 * ks + 0) ^ grp)) * 4 + tg];
                    const float v1 = sA[(base + ((2 * ks + 1) ^ grp)) * 4 + tg];
                    af[mt][i]     = CVTA ? f2tf32(v0) : __float_as_uint(v0);
                    af[mt][i + 2] = CVTA ? f2tf32(v1) : __float_as_uint(v1);
                }
            }
            uint32_t bf[8][2];
#pragma unroll
            for (int nt = 0; nt < 8; nt++) {
                const int base = ((wn >> 3) + nt) * 64 + grp * 8;
                bf[nt][0] = __float_as_uint(sB[(base + ((2 * ks + 0) ^ grp)) * 4 + tg]);
                bf[nt][1] = __float_as_uint(sB[(base + ((2 * ks + 1) ^ grp)) * 4 + tg]);
            }
#pragma unroll
            for (int mt = 0; mt < 4; mt++)
#pragma unroll
                for (int nt = 0; nt < 8; nt++)
                    mma_tf32(acc[mt][nt][0], acc[mt][nt][1], acc[mt][nt][2], acc[mt][nt][3],
                             af[mt][0], af[mt][1], af[mt][2], af[mt][3],
                             bf[nt][0], bf[nt][1]);
        }
        cbuf++; if (cbuf >= NSTAGE) cbuf = 0;
    }

    // ---- epilogue ----
    if (MODE == 1) {
        // scores: write exp(score), accumulate per-row partial sums over this
        // warp's 64 columns, store to aux[row*64 + ct].
        const int ct = (int)((bn + wn) >> 6);
#pragma unroll
        for (int mt = 0; mt < 4; mt++) {
            const long r0 = bm + wm + mt * 16 + grp;
            float rs0 = 0.0f, rs1 = 0.0f;
#pragma unroll
            for (int nt = 0; nt < 8; nt++) {
                const int cn = (int)bn + wn + nt * 8 + 2 * tg;
                float2 v0, v1;
                v0.x = __expf(acc[mt][nt][0] * alpha);
                v0.y = __expf(acc[mt][nt][1] * alpha);
                v1.x = __expf(acc[mt][nt][2] * alpha);
                v1.y = __expf(acc[mt][nt][3] * alpha);
                rs0 += v0.x + v0.y;
                rs1 += v1.x + v1.y;
                *(float2*)(C + r0 * (long)ldc + cn)       = v0;
                *(float2*)(C + (r0 + 8) * (long)ldc + cn) = v1;
            }
            rs0 += __shfl_xor_sync(0xffffffffu, rs0, 1);
            rs0 += __shfl_xor_sync(0xffffffffu, rs0, 2);
            rs1 += __shfl_xor_sync(0xffffffffu, rs1, 1);
            rs1 += __shfl_xor_sync(0xffffffffu, rs1, 2);
            if (tg == 0) {
                aux[(size_t)r0 * 64 + ct]       = rs0;
                aux[(size_t)(r0 + 8) * 64 + ct] = rs1;
            }
        }
    } else {
#pragma unroll
        for (int mt = 0; mt < 4; mt++) {
            const long r0 = bm + wm + mt * 16 + grp;
            float s0 = 1.0f, s1 = 1.0f;
            if (MODE == 2) {
                s0 = invrow[r0];
                s1 = invrow[r0 + 8];
            }
#pragma unroll
            for (int nt = 0; nt < 8; nt++) {
                const int cn = (int)bn + wn + nt * 8 + 2 * tg;
                float2 v0, v1;
                v0.x = acc[mt][nt][0] * alpha;
                v0.y = acc[mt][nt][1] * alpha;
                v1.x = acc[mt][nt][2] * alpha;
                v1.y = acc[mt][nt][3] * alpha;
                if (MODE == 2) {
                    v0.x *= s0; v0.y *= s0;
                    v1.x *= s1; v1.y *= s1;
                }
                if (HASBIAS) {
                    const float b0 = bias[cn], b1 = bias[cn + 1];
                    v0.x += b0; v0.y += b1;
                    v1.x += b0; v1.y += b1;
                }
                if (ROUND_OUT) {
                    v0.x = roundtf(v0.x); v0.y = roundtf(v0.y);
                    v1.x = roundtf(v1.x); v1.y = roundtf(v1.y);
                }
                *(float2*)(C + r0 * (long)ldc + cn)       = v0;
                *(float2*)(C + (r0 + 8) * (long)ldc + cn) = v1;
            }
        }
    }
}

// ---------------------------------------------------------------------------
// transpose (+tf32 round): dst[c][r] = round(src[r][c])
// ---------------------------------------------------------------------------
__global__ void __launch_bounds__(256) trans_kernel(const float* __restrict__ in,
                                                    int which, int R, int C)
{
    __shared__ float t[32][33];
    const int z = blockIdx.z;
    const float* src;
    float* dst;
    if (which == 4)      { src = g_V + (size_t)z * R * C;  dst = g_VT + (size_t)z * R * C; }
    else if (which == 3) { src = in;                        dst = g_WoT; }
    else                 { src = in + (size_t)z * R * C;    dst = g_WT + ((size_t)which * NH + z) * R * C; }

    const int c0 = blockIdx.x * 32, r0 = blockIdx.y * 32;
    const int tx = threadIdx.x & 31, ty = threadIdx.x >> 5;
#pragma unroll
    for (int i = 0; i < 4; i++)
        t[ty + i * 8][tx] = roundtf(src[(size_t)(r0 + ty + i * 8) * C + c0 + tx]);
    __syncthreads();
#pragma unroll
    for (int i = 0; i < 4; i++)
        dst[(size_t)(c0 + ty + i * 8) * R + r0 + tx] = t[tx][ty + i * 8];
}

// ---------------------------------------------------------------------------
// invsum: one warp per attn row; 64 partials -> 1/rowsum
// ---------------------------------------------------------------------------
__global__ void __launch_bounds__(256) invsum_kernel()
{
    const int row  = blockIdx.x * 8 + (threadIdx.x >> 5);
    const int lane = threadIdx.x & 31;
    float s = g_psum[(size_t)row * 64 + lane] + g_psum[(size_t)row * 64 + 32 + lane];
#pragma unroll
    for (int o = 16; o > 0; o >>= 1) s += __shfl_xor_sync(0xffffffffu, s, o);
    if (lane == 0) g_invsum[row] = 1.0f / s;
}

// ---------------------------------------------------------------------------
__global__ void __launch_bounds__(256, 1) proj_tc(
    const float* __restrict__ q, const float* __restrict__ k, const float* __restrict__ v,
    const float* __restrict__ bq, const float* __restrict__ bk, const float* __restrict__ bv)
{
    const int z = blockIdx.z, mat = z >> 2, head = z & 3;
    const float* A    = mat == 0 ? q  : mat == 1 ? k  : v;
    const float* B    = g_WT + (size_t)z * DK * DM;
    const float* bias = (mat == 0 ? bq : mat == 1 ? bk : bv) + head * DK;
    float* C = (mat == 0 ? g_Q : mat == 1 ? g_K : g_V) + (size_t)head * BS_TOT * DK;
    gemm_cp<2, 4, true, true, true, 0>(A, DM, B, DM, C, DK, DM, 1.0f, bias,
                                       nullptr, nullptr);
}

__global__ void __launch_bounds__(256, 1) scores_tc(float* __restrict__ attn_out)
{
    float* attn = attn_out ? attn_out : g_attn_fallback;
    const int z = blockIdx.z;
    gemm_cp<4, 2, false, false, false, 1>(g_Q + (size_t)z * SEQ * DK, DK,
                                          g_K + (size_t)z * SEQ * DK, DK,
                                          attn + (size_t)z * SEQ * SEQ, SEQ, DK, 0.0625f,
                                          nullptr, g_psum + (size_t)z * SEQ * 64, nullptr);
}

__global__ void __launch_bounds__(256, 1) av_tc(float* __restrict__ attn_out)
{
    float* attn = attn_out ? attn_out : g_attn_fallback;
    const int z = blockIdx.z, h = z >> 1, b = z & 1;
    gemm_cp<2, 4, true, false, true, 2>(attn + (size_t)z * SEQ * SEQ, SEQ,
                                        g_VT + (size_t)z * DK * SEQ, SEQ,
                                        g_HO + (size_t)b * SEQ * DM + h * DK, DM, SEQ, 1.0f,
                                        nullptr,
                                        attn + (size_t)z * SEQ * SEQ,
                                        g_invsum + (size_t)z * SEQ);
}

__global__ void __launch_bounds__(256, 1) outproj_tc(const float* __restrict__ bo,
                                                     float* __restrict__ out)
{
    gemm_cp<2, 4, false, true, false, 0>(g_HO, DM, g_WoT, DM, out, DM, DM, 1.0f, bo,
                                         nullptr, nullptr);
}

// ---------------------------------------------------------------------------
extern "C" void kernel_launch(void* const* d_in, const int* in_sizes, int n_in,
                              void* d_out, int out_size)
{
    const float* q  = (const float*)d_in[0];
    const float* k  = (const float*)d_in[1];
    const float* v  = (const float*)d_in[2];
    const float* Wq = (const float*)d_in[3];
    const float* bq = (const float*)d_in[4];
    const float* Wk = (const float*)d_in[5];
    const float* bk = (const float*)d_in[6];
    const float* Wv = (const float*)d_in[7];
    const float* bv = (const float*)d_in[8];
    const float* Wo = (const float*)d_in[9];
    const float* bo = (const float*)d_in[10];

    float* out = (float*)d_out;
    const long OUT_ELEMS  = (long)NB * SEQ * DM;
    const long ATTN_ELEMS = (long)NH * NB * SEQ * SEQ;
    float* attn_out = nullptr;
    if ((long)out_size >= OUT_ELEMS + ATTN_ELEMS) attn_out = out + OUT_ELEMS;

    cudaFuncSetAttribute(proj_tc,    cudaFuncAttributeMaxDynamicSharedMemorySize, SMEM_BYTES);
    cudaFuncSetAttribute(scores_tc,  cudaFuncAttributeMaxDynamicSharedMemorySize, SMEM_BYTES);
    cudaFuncSetAttribute(av_tc,      cudaFuncAttributeMaxDynamicSharedMemorySize, SMEM_BYTES);
    cudaFuncSetAttribute(outproj_tc, cudaFuncAttributeMaxDynamicSharedMemorySize, SMEM_BYTES);

    trans_kernel<<<dim3(8, 32, 4),  256>>>(Wq, 0, DM, DK);
    trans_kernel<<<dim3(8, 32, 4),  256>>>(Wk, 1, DM, DK);
    trans_kernel<<<dim3(8, 32, 4),  256>>>(Wv, 2, DM, DK);
    trans_kernel<<<dim3(32, 32, 1), 256>>>(Wo, 3, DM, DM);

    proj_tc<<<dim3(1, 64, 12), 256, SMEM_BYTES>>>(q, k, v, bq, bk, bv);

    trans_kernel<<<dim3(8, 128, 8), 256>>>(nullptr, 4, SEQ, DK);

    // scores: writes exp + partial sums
    scores_tc<<<dim3(32, 16, 8), 256, SMEM_BYTES>>>(attn_out);

    // 1/rowsum
    invsum_kernel<<<dim3(NROWS / 8), 256>>>();

    // av: normalizes attn in-place + computes HO
    av_tc<<<dim3(1, 32, 8), 256, SMEM_BYTES>>>(attn_out);

    outproj_tc<<<dim3(4, 64, 1), 256, SMEM_BYTES>>>(bo, out);
}

// round 9
// speedup vs baseline: 1.4999x; 1.3440x over previous
#include <cuda_runtime.h>
#include <cuda_fp16.h>
#include <cstdint>
#include <math.h>

// ---------------------------------------------------------------------------
// LegalMultiHeadAttention — Round 9: full fp16 m16n8k16 tensor path
// (same 10-bit mantissa as tf32, fp32 accum), fp16 operands in smem+global.
// Fused softmax from R8 kept: scores writes unnormalized exp (fp16) + psum,
// invsum computes 1/rowsum, av normalizes (fp32 attn out) + computes HO.
//   B=2, S=4096, D_MODEL=1024, H=4, D_K=256.
// ---------------------------------------------------------------------------

#define SEQ    4096
#define DK     256
#define DM     1024
#define NH     4
#define NB     2
#define BS_TOT (NB*SEQ)          // 8192
#define NROWS  (NH*NB*SEQ)       // 32768

// --- fp16 scratch (allocation-free rule) ---
__device__ __half g_qin[(size_t)BS_TOT*DM];
__device__ __half g_kin[(size_t)BS_TOT*DM];
__device__ __half g_vin[(size_t)BS_TOT*DM];
__device__ __half g_Qh [(size_t)NH*BS_TOT*DK];
__device__ __half g_Kh [(size_t)NH*BS_TOT*DK];
__device__ __half g_Vh [(size_t)NH*BS_TOT*DK];
__device__ __half g_VTh[(size_t)NH*BS_TOT*DK];
__device__ __half g_HOh[(size_t)BS_TOT*DM];
__device__ __half g_WTh[(size_t)3*NH*DK*DM];
__device__ __half g_WoTh[(size_t)DM*DM];
__device__ __half g_Eh [(size_t)NH*NB*SEQ*SEQ];   // unnormalized exp
__device__ float  g_psum[(size_t)NROWS*64];
__device__ float  g_invsum[NROWS];
__device__ float  g_attn_fallback[(size_t)NH*NB*SEQ*SEQ];

__device__ __forceinline__ uint32_t smem_u32(const void* p) {
    uint32_t a;
    asm("{ .reg .u64 t; cvta.to.shared.u64 t, %1; cvt.u32.u64 %0, t; }"
        : "=r"(a) : "l"(p));
    return a;
}
__device__ __forceinline__ void mma_f16(float& c0, float& c1, float& c2, float& c3,
                                        uint32_t a0, uint32_t a1, uint32_t a2, uint32_t a3,
                                        uint32_t b0, uint32_t b1) {
    asm volatile(
        "mma.sync.aligned.m16n8k16.row.col.f32.f16.f16.f32 "
        "{%0,%1,%2,%3}, {%4,%5,%6,%7}, {%8,%9}, {%0,%1,%2,%3};"
        : "+f"(c0), "+f"(c1), "+f"(c2), "+f"(c3)
        : "r"(a0), "r"(a1), "r"(a2), "r"(a3), "r"(b0), "r"(b1));
}
__device__ __forceinline__ void cp16(uint32_t dst, const void* src) {
    asm volatile("cp.async.cg.shared.global [%0], [%1], 16;" :: "r"(dst), "l"(src));
}

#define NSTAGE 3
#define BUF_WORDS 6144                       // 384 rows * 16 words (32 fp16)
#define SMEM_BYTES (NSTAGE*BUF_WORDS*4)      // 73728

// ---------------------------------------------------------------------------
// fp16 GEMM NT: C[m,n] = alpha*sum_k A[m,k]*B[n,k] (+bias[n]).
// 256 threads = 8 warps (WGM x WGN), warp tile 64x64, K staged 32/stage.
// smem: 16 uint32 words per row-stage; word kp swizzled by ((row>>1)&3)<<2.
// MODE 0 plain | 1 scores (exp+psum) | 2 av (attn writeback + invrow scale)
// ---------------------------------------------------------------------------
template<int WGM, int WGN, bool HASBIAS, bool OUTHALF, int MODE>
__device__ __forceinline__ void gemm_h(const __half* __restrict__ A, int lda,
                                       const __half* __restrict__ B, int ldb,
                                       void* __restrict__ Cv, int ldc,
                                       int K, float alpha, const float* __restrict__ bias,
                                       float* __restrict__ aux,
                                       const float* __restrict__ invrow)
{
    extern __shared__ uint32_t smem[];
    const uint32_t sbase = smem_u32(smem);

    const int tid  = threadIdx.x;           // 256
    const int wid  = tid >> 5;
    const int lane = tid & 31;
    const int grp  = lane >> 2;
    const int tg   = lane & 3;
    const int wm   = (wid / WGN) * 64;
    const int wn   = (wid % WGN) * 64;

    const long bm = (long)blockIdx.y * (WGM * 64);
    const long bn = (long)blockIdx.x * (WGN * 64);
    A += bm * (long)lda;
    B += bn * (long)ldb;

    const int sm4 = tid >> 2;                // 0..63 (row within 64-row pass)
    const int c4  = tid & 3;                 // 16B chunk

    float invs[WGM > 0 ? WGM : 1];
    if (MODE == 2) {
#pragma unroll
        for (int c = 0; c < WGM; c++)
            invs[c] = invrow[bm + sm4 + c * 64];
    }

    float acc[4][8][4];
#pragma unroll
    for (int i = 0; i < 4; i++)
#pragma unroll
        for (int j = 0; j < 8; j++)
#pragma unroll
            for (int r = 0; r < 4; r++) acc[i][j][r] = 0.0f;

    const int NIT = K >> 5;
    const int AWORDS = WGM * 64 * 16;

    auto stage_copy = [&](int stage, int buf) {
        const uint32_t db = sbase + (uint32_t)buf * (BUF_WORDS * 4);
        const __half* Ak = A + stage * 32 + c4 * 8;
        const __half* Bk = B + stage * 32 + c4 * 8;
#pragma unroll
        for (int c = 0; c < WGM; c++) {      // A: WGM*64 rows
            const int r = sm4 + c * 64;
            const int w = r * 16 + ((c4 * 4) ^ (((r >> 1) & 3) << 2));
            cp16(db + (uint32_t)w * 4, Ak + (long)r * lda);
        }
        const uint32_t dbB = db + (uint32_t)AWORDS * 4;
#pragma unroll
        for (int c = 0; c < WGN; c++) {      // B: WGN*64 rows
            const int r = sm4 + c * 64;
            const int w = r * 16 + ((c4 * 4) ^ (((r >> 1) & 3) << 2));
            cp16(dbB + (uint32_t)w * 4, Bk + (long)r * ldb);
        }
        asm volatile("cp.async.commit_group;" ::: "memory");
    };

    stage_copy(0, 0);
    stage_copy(1, 1);

    int cbuf = 0;
#pragma unroll 1
    for (int it = 0; it < NIT; it++) {
        asm volatile("cp.async.wait_group %0;" :: "n"(NSTAGE - 2) : "memory");
        __syncthreads();
        if (it + 2 < NIT) {
            int nb = cbuf + 2; if (nb >= NSTAGE) nb -= NSTAGE;
            stage_copy(it + 2, nb);
        }

        const uint32_t* sA = smem + cbuf * BUF_WORDS;
        const uint32_t* sB = sA + AWORDS;

        // MODE 2: write normalized fp32 attn back (each element staged once)
        if (MODE == 2) {
#pragma unroll
            for (int c = 0; c < WGM; c++) {
                const int m = sm4 + c * 64;
                const int w = m * 16 + ((c4 * 4) ^ (((m >> 1) & 3) << 2));
                const uint4 d = *reinterpret_cast<const uint4*>(sA + w);
                const float iv = invs[c];
                float2 f0 = __half22float2(*reinterpret_cast<const __half2*>(&d.x));
                float2 f1 = __half22float2(*reinterpret_cast<const __half2*>(&d.y));
                float2 f2 = __half22float2(*reinterpret_cast<const __half2*>(&d.z));
                float2 f3 = __half22float2(*reinterpret_cast<const __half2*>(&d.w));
                float4 o0 = make_float4(f0.x * iv, f0.y * iv, f1.x * iv, f1.y * iv);
                float4 o1 = make_float4(f2.x * iv, f2.y * iv, f3.x * iv, f3.y * iv);
                float* dst = aux + (bm + m) * (long)lda + it * 32 + c4 * 8;
                *reinterpret_cast<float4*>(dst)     = o0;
                *reinterpret_cast<float4*>(dst + 4) = o1;
            }
        }

#pragma unroll
        for (int ks = 0; ks < 2; ks++) {     // two k16 steps per 32-K stage
            const int kb = ks * 8;
            uint32_t af[4][4];
#pragma unroll
            for (int mt = 0; mt < 4; mt++) {
                const int r0 = wm + mt * 16 + grp;
                const int r1 = r0 + 8;
                const int s0 = ((r0 >> 1) & 3) << 2;
                const int s1 = ((r1 >> 1) & 3) << 2;
                af[mt][0] = sA[r0 * 16 + ((kb + tg)     ^ s0)];
                af[mt][1] = sA[r1 * 16 + ((kb + tg)     ^ s1)];
                af[mt][2] = sA[r0 * 16 + ((kb + tg + 4) ^ s0)];
                af[mt][3] = sA[r1 * 16 + ((kb + tg + 4) ^ s1)];
            }
            uint32_t bf[8][2];
#pragma unroll
            for (int nt = 0; nt < 8; nt++) {
                const int rb = wn + nt * 8 + grp;
                const int sb = ((rb >> 1) & 3) << 2;
                bf[nt][0] = sB[rb * 16 + ((kb + tg)     ^ sb)];
                bf[nt][1] = sB[rb * 16 + ((kb + tg + 4) ^ sb)];
            }
#pragma unroll
            for (int mt = 0; mt < 4; mt++)
#pragma unroll
                for (int nt = 0; nt < 8; nt++)
                    mma_f16(acc[mt][nt][0], acc[mt][nt][1], acc[mt][nt][2], acc[mt][nt][3],
                            af[mt][0], af[mt][1], af[mt][2], af[mt][3],
                            bf[nt][0], bf[nt][1]);
        }
        cbuf++; if (cbuf >= NSTAGE) cbuf = 0;
    }

    // ---- epilogue ----
    if (MODE == 1) {
        __half* Ch = (__half*)Cv;
        const int ct = (int)((bn + wn) >> 6);
#pragma unroll
        for (int mt = 0; mt < 4; mt++) {
            const long r0 = bm + wm + mt * 16 + grp;
            float rs0 = 0.0f, rs1 = 0.0f;
#pragma unroll
            for (int nt = 0; nt < 8; nt++) {
                const int cn = (int)bn + wn + nt * 8 + 2 * tg;
                const float e00 = __expf(acc[mt][nt][0] * alpha);
                const float e01 = __expf(acc[mt][nt][1] * alpha);
                const float e10 = __expf(acc[mt][nt][2] * alpha);
                const float e11 = __expf(acc[mt][nt][3] * alpha);
                const __half2 h0 = __floats2half2_rn(e00, e01);
                const __half2 h1 = __floats2half2_rn(e10, e11);
                const float2 b0 = __half22float2(h0);   // rounded values for psum
                const float2 b1 = __half22float2(h1);
                rs0 += b0.x + b0.y;
                rs1 += b1.x + b1.y;
                *reinterpret_cast<__half2*>(Ch + r0 * (long)ldc + cn)       = h0;
                *reinterpret_cast<__half2*>(Ch + (r0 + 8) * (long)ldc + cn) = h1;
            }
            rs0 += __shfl_xor_sync(0xffffffffu, rs0, 1);
            rs0 += __shfl_xor_sync(0xffffffffu, rs0, 2);
            rs1 += __shfl_xor_sync(0xffffffffu, rs1, 1);
            rs1 += __shfl_xor_sync(0xffffffffu, rs1, 2);
            if (tg == 0) {
                aux[(size_t)r0 * 64 + ct]       = rs0;
                aux[(size_t)(r0 + 8) * 64 + ct] = rs1;
            }
        }
    } else {
#pragma unroll
        for (int mt = 0; mt < 4; mt++) {
            const long r0 = bm + wm + mt * 16 + grp;
            float s0 = 1.0f, s1 = 1.0f;
            if (MODE == 2) { s0 = invrow[r0]; s1 = invrow[r0 + 8]; }
#pragma unroll
            for (int nt = 0; nt < 8; nt++) {
                const int cn = (int)bn + wn + nt * 8 + 2 * tg;
                float v00 = acc[mt][nt][0] * alpha * s0;
                float v01 = acc[mt][nt][1] * alpha * s0;
                float v10 = acc[mt][nt][2] * alpha * s1;
                float v11 = acc[mt][nt][3] * alpha * s1;
                if (HASBIAS) {
                    const float b0 = bias[cn], b1 = bias[cn + 1];
                    v00 += b0; v01 += b1;
                    v10 += b0; v11 += b1;
                }
                if (OUTHALF) {
                    __half* Ch = (__half*)Cv;
                    *reinterpret_cast<__half2*>(Ch + r0 * (long)ldc + cn)       = __floats2half2_rn(v00, v01);
                    *reinterpret_cast<__half2*>(Ch + (r0 + 8) * (long)ldc + cn) = __floats2half2_rn(v10, v11);
                } else {
                    float* Cf = (float*)Cv;
                    *reinterpret_cast<float2*>(Cf + r0 * (long)ldc + cn)       = make_float2(v00, v01);
                    *reinterpret_cast<float2*>(Cf + (r0 + 8) * (long)ldc + cn) = make_float2(v10, v11);
                }
            }
        }
    }
}

// ---------------------------------------------------------------------------
// q/k/v fp32 -> fp16 (layout-preserving)
// ---------------------------------------------------------------------------
__global__ void __launch_bounds__(256) f2h_kernel(const float* __restrict__ q,
                                                  const float* __restrict__ k,
                                                  const float* __restrict__ v)
{
    const int z = blockIdx.y;
    const float* src = z == 0 ? q : z == 1 ? k : v;
    __half* dst = z == 0 ? g_qin : z == 1 ? g_kin : g_vin;
    const size_t i = (size_t)blockIdx.x * 256 + threadIdx.x;   // float4 index
    const float4 val = reinterpret_cast<const float4*>(src)[i];
    __half2 h0 = __floats2half2_rn(val.x, val.y);
    __half2 h1 = __floats2half2_rn(val.z, val.w);
    uint2 o;
    o.x = *reinterpret_cast<uint32_t*>(&h0);
    o.y = *reinterpret_cast<uint32_t*>(&h1);
    reinterpret_cast<uint2*>(dst)[i] = o;
}

// ---------------------------------------------------------------------------
// weight transpose fp32 -> fp16: dst[c][r] = half(src[r][c])
// which 0/1/2: Wq/Wk/Wv [H][R][C]; which 3: Wo
// ---------------------------------------------------------------------------
__global__ void __launch_bounds__(256) transw_kernel(const float* __restrict__ in,
                                                     int which, int R, int C)
{
    __shared__ float t[32][33];
    const int z = blockIdx.z;
    const float* src;
    __half* dst;
    if (which == 3) { src = in; dst = g_WoTh; }
    else            { src = in + (size_t)z * R * C; dst = g_WTh + ((size_t)which * NH + z) * R * C; }

    const int c0 = blockIdx.x * 32, r0 = blockIdx.y * 32;
    const int tx = threadIdx.x & 31, ty = threadIdx.x >> 5;
#pragma unroll
    for (int i = 0; i < 4; i++)
        t[ty + i * 8][tx] = src[(size_t)(r0 + ty + i * 8) * C + c0 + tx];
    __syncthreads();
#pragma unroll
    for (int i = 0; i < 4; i++)
        dst[(size_t)(c0 + ty + i * 8) * R + r0 + tx] = __float2half_rn(t[tx][ty + i * 8]);
}

// ---------------------------------------------------------------------------
// V (fp16 [z][SEQ][DK]) -> VT (fp16 [z][DK][SEQ])
// ---------------------------------------------------------------------------
__global__ void __launch_bounds__(256) transv_kernel()
{
    __shared__ __half t[32][34];
    const int z = blockIdx.z;
    const __half* src = g_Vh + (size_t)z * SEQ * DK;
    __half* dst = g_VTh + (size_t)z * SEQ * DK;
    const int c0 = blockIdx.x * 32, r0 = blockIdx.y * 32;
    const int tx = threadIdx.x & 31, ty = threadIdx.x >> 5;
#pragma unroll
    for (int i = 0; i < 4; i++)
        t[ty + i * 8][tx] = src[(size_t)(r0 + ty + i * 8) * DK + c0 + tx];
    __syncthreads();
#pragma unroll
    for (int i = 0; i < 4; i++)
        dst[(size_t)(c0 + ty + i * 8) * SEQ + r0 + tx] = t[tx][ty + i * 8];
}

// ---------------------------------------------------------------------------
// invsum: one warp per attn row; 64 partials -> 1/rowsum
// ---------------------------------------------------------------------------
__global__ void __launch_bounds__(256) invsum_kernel()
{
    const int row  = blockIdx.x * 8 + (threadIdx.x >> 5);
    const int lane = threadIdx.x & 31;
    float s = g_psum[(size_t)row * 64 + lane] + g_psum[(size_t)row * 64 + 32 + lane];
#pragma unroll
    for (int o = 16; o > 0; o >>= 1) s += __shfl_xor_sync(0xffffffffu, s, o);
    if (lane == 0) g_invsum[row] = 1.0f / s;
}

// ---------------------------------------------------------------------------
// GEMM wrappers
// ---------------------------------------------------------------------------
__global__ void __launch_bounds__(256, 1) proj_tc(
    const float* __restrict__ bq, const float* __restrict__ bk, const float* __restrict__ bv)
{
    const int z = blockIdx.z, mat = z >> 2, head = z & 3;
    const __half* A    = mat == 0 ? g_qin : mat == 1 ? g_kin : g_vin;
    const __half* B    = g_WTh + (size_t)z * DK * DM;
    const float*  bias = (mat == 0 ? bq : mat == 1 ? bk : bv) + head * DK;
    __half* C = (mat == 0 ? g_Qh : mat == 1 ? g_Kh : g_Vh) + (size_t)head * BS_TOT * DK;
    gemm_h<2, 4, true, true, 0>(A, DM, B, DM, C, DK, DM, 1.0f, bias, nullptr, nullptr);
}

__global__ void __launch_bounds__(256, 1) scores_tc()
{
    const int z = blockIdx.z;
    gemm_h<4, 2, false, true, 1>(g_Qh + (size_t)z * SEQ * DK, DK,
                                 g_Kh + (size_t)z * SEQ * DK, DK,
                                 g_Eh + (size_t)z * SEQ * SEQ, SEQ, DK, 0.0625f,
                                 nullptr, g_psum + (size_t)z * SEQ * 64, nullptr);
}

__global__ void __launch_bounds__(256, 1) av_tc(float* __restrict__ attn_out)
{
    float* attn = attn_out ? attn_out : g_attn_fallback;
    const int z = blockIdx.z, h = z >> 1, b = z & 1;
    gemm_h<2, 4, false, true, 2>(g_Eh + (size_t)z * SEQ * SEQ, SEQ,
                                 g_VTh + (size_t)z * DK * SEQ, SEQ,
                                 g_HOh + (size_t)b * SEQ * DM + h * DK, DM, SEQ, 1.0f,
                                 nullptr,
                                 attn + (size_t)z * SEQ * SEQ,
                                 g_invsum + (size_t)z * SEQ);
}

__global__ void __launch_bounds__(256, 1) outproj_tc(const float* __restrict__ bo,
                                                     float* __restrict__ out)
{
    gemm_h<2, 4, true, false, 0>(g_HOh, DM, g_WoTh, DM, out, DM, DM, 1.0f, bo,
                                 nullptr, nullptr);
}

// ---------------------------------------------------------------------------
extern "C" void kernel_launch(void* const* d_in, const int* in_sizes, int n_in,
                              void* d_out, int out_size)
{
    const float* q  = (const float*)d_in[0];
    const float* k  = (const float*)d_in[1];
    const float* v  = (const float*)d_in[2];
    const float* Wq = (const float*)d_in[3];
    const float* bq = (const float*)d_in[4];
    const float* Wk = (const float*)d_in[5];
    const float* bk = (const float*)d_in[6];
    const float* Wv = (const float*)d_in[7];
    const float* bv = (const float*)d_in[8];
    const float* Wo = (const float*)d_in[9];
    const float* bo = (const float*)d_in[10];

    float* out = (float*)d_out;
    const long OUT_ELEMS  = (long)NB * SEQ * DM;
    const long ATTN_ELEMS = (long)NH * NB * SEQ * SEQ;
    float* attn_out = nullptr;
    if ((long)out_size >= OUT_ELEMS + ATTN_ELEMS) attn_out = out + OUT_ELEMS;

    cudaFuncSetAttribute(proj_tc,    cudaFuncAttributeMaxDynamicSharedMemorySize, SMEM_BYTES);
    cudaFuncSetAttribute(scores_tc,  cudaFuncAttributeMaxDynamicSharedMemorySize, SMEM_BYTES);
    cudaFuncSetAttribute(av_tc,      cudaFuncAttributeMaxDynamicSharedMemorySize, SMEM_BYTES);
    cudaFuncSetAttribute(outproj_tc, cudaFuncAttributeMaxDynamicSharedMemorySize, SMEM_BYTES);

    // inputs -> fp16
    f2h_kernel<<<dim3(BS_TOT * DM / 4 / 256, 3), 256>>>(q, k, v);

    // weights -> fp16 transposed
    transw_kernel<<<dim3(8, 32, 4),  256>>>(Wq, 0, DM, DK);
    transw_kernel<<<dim3(8, 32, 4),  256>>>(Wk, 1, DM, DK);
    transw_kernel<<<dim3(8, 32, 4),  256>>>(Wv, 2, DM, DK);
    transw_kernel<<<dim3(32, 32, 1), 256>>>(Wo, 3, DM, DM);

    // Q/K/V projections (128x256 tiles)
    proj_tc<<<dim3(1, 64, 12), 256, SMEM_BYTES>>>(bq, bk, bv);

    // V -> VT
    transv_kernel<<<dim3(8, 128, 8), 256>>>();

    // scores: exp(QK^T/16) fp16 + row partial sums (256x128 tiles)
    scores_tc<<<dim3(32, 16, 8), 256, SMEM_BYTES>>>();

    // 1/rowsum
    invsum_kernel<<<dim3(NROWS / 8), 256>>>();

    // av: normalized attn (fp32, to d_out) + HO (128x256 tiles)
    av_tc<<<dim3(1, 32, 8), 256, SMEM_BYTES>>>(attn_out);

    // out = concat @ Wo + bo
    outproj_tc<<<dim3(4, 64, 1), 256, SMEM_BYTES>>>(bo, out);
}